// round 2
// baseline (speedup 1.0000x reference)
#include <cuda_runtime.h>
#include <math.h>

// Problem constants
#define BATCH 8192
#define DIM   2048
#define NE    8
#define NG    4
#define PP    512
#define HH    192
// capacity for expert-grouped assignment list: 2*BATCH real + up to 63 pad per expert
#define CAP   17408
#define MT_MAX 272   // CAP/64

// ---------------- device scratch (static, no allocation) ----------------
__device__ int   g_count[NE];
__device__ int   g_cursor[NE];
__device__ int   g_padOff[NE + 1];
__device__ int   g_Mtot;
__device__ int   g_routeE[2 * BATCH];
__device__ float g_routeW[2 * BATCH];
__device__ int   g_assignRow[CAP];
__device__ float g_assignW[CAP];
__device__ float g_H[(size_t)CAP * PP];   // hidden activations per assignment

// ---------------- init: zero output + scratch ----------------
__global__ __launch_bounds__(256) void init_kernel(float4* __restrict__ out4) {
    int i = blockIdx.x * 256 + threadIdx.x;           // 16384 * 256 = BATCH*DIM/4
    if (i < (BATCH * DIM) / 4) out4[i] = make_float4(0.f, 0.f, 0.f, 0.f);
    if (i < CAP) { g_assignRow[i] = -1; g_assignW[i] = 0.f; }
    if (i < NE)  { g_count[i] = 0; g_cursor[i] = 0; }
}

// ---------------- routing ----------------
// qm: XLA-GPU-style fp32 tree reduction (vec2 pair add -> warp shfl tree ->
//     cross-warp tree). Lane-0 tree pairing identical for xor/down variants.
// m, logits, softmax, top-2: double precision (immune to --use_fast_math;
//     trig at |ang| up to ~120 rad needs exact range reduction).
__global__ __launch_bounds__(1024) void route_kernel(
    const float* __restrict__ x,
    const float* __restrict__ Wg, const float* __restrict__ bg,
    const float* __restrict__ Wp, const float* __restrict__ bp,
    const float* __restrict__ Wgg, const float* __restrict__ bgg)
{
    __shared__ float  warpSum[32];
    __shared__ double dWarp[32];
    __shared__ float  sh_qm;
    int b = blockIdx.x, tid = threadIdx.x;

    // ---- qm: fp32 tree matching XLA row-reduce (1024 lanes x vec2) ----
    const float2* xr = (const float2*)(x + (size_t)b * DIM);
    float2 v = xr[tid];
    float acc = v.x + v.y;
    #pragma unroll
    for (int o = 16; o; o >>= 1) acc += __shfl_down_sync(0xffffffffu, acc, o);
    if ((tid & 31) == 0) warpSum[tid >> 5] = acc;
    __syncthreads();
    if (tid < 32) {
        float a2 = warpSum[tid];
        #pragma unroll
        for (int o = 16; o; o >>= 1) a2 += __shfl_down_sync(0xffffffffu, a2, o);
        if (tid == 0) sh_qm = a2 * (1.0f / 2048.0f);   // power-of-two: exact
    }
    __syncthreads();
    float qm = sh_qm;

    // ---- temporal mean in double; ang rounded to fp32 first (matches JAX's
    //      fp32 multiply qm*freq), trig in double ----
    double tr = 0.0;
    if (tid < HH) {
        float ang = __fmul_rn(qm, (float)(7 * (tid + 1)));
        double da = (double)ang;
        tr = cos(da) + sin(da);
    }
    #pragma unroll
    for (int o = 16; o; o >>= 1) tr += __shfl_down_sync(0xffffffffu, tr, o);
    if ((tid & 31) == 0) dWarp[tid >> 5] = tr;
    __syncthreads();

    if (tid == 0) {
        double t = 0.0;
        #pragma unroll
        for (int i = 0; i < 32; i++) t += dWarp[i];
        double m = t / 384.0;
        const double c = 0.015625;   // KTOP/D: LIF spike rate mean is exactly constant

        double l[NE]; double mx = -1e300;
        #pragma unroll
        for (int e = 0; e < NE; e++) {
            int g = e & (NG - 1);
            double v2 = (m * (double)Wg[e] + c * (double)Wg[NE + e] + (double)bg[e])
                      - 0.1 * (m * (double)Wp[e] + c * (double)Wp[NE + e] + (double)bp[e])
                      + (m * (double)Wgg[g] + c * (double)Wgg[NG + g] + (double)bgg[g]);
            l[e] = v2; mx = fmax(mx, v2);
        }
        double sf[NE], Z = 0.0;
        #pragma unroll
        for (int e = 0; e < NE; e++) { sf[e] = exp(l[e] - mx); Z += sf[e]; }
        // top-2: strict >, first index wins on ties (matches jax.lax.top_k)
        int e0 = 0;
        #pragma unroll
        for (int e = 1; e < NE; e++) if (sf[e] > sf[e0]) e0 = e;
        int e1 = (e0 == 0) ? 1 : 0;
        #pragma unroll
        for (int e = 0; e < NE; e++) if (e != e0 && sf[e] > sf[e1]) e1 = e;
        double s0 = sf[e0] / Z, s1 = sf[e1] / Z;
        double den = s0 + s1 + 1e-9;
        float w0 = (float)(s0 / den), w1 = (float)(s1 / den);

        g_routeE[2 * b] = e0; g_routeE[2 * b + 1] = e1;
        g_routeW[2 * b] = w0; g_routeW[2 * b + 1] = w1;
        atomicAdd(&g_count[e0], 1);
        atomicAdd(&g_count[e1], 1);
    }
}

// ---------------- scan: padded per-expert segment offsets ----------------
__global__ void scan_kernel() {
    if (blockIdx.x == 0 && threadIdx.x == 0) {
        int off = 0;
        #pragma unroll
        for (int e = 0; e < NE; e++) {
            g_padOff[e] = off;
            off += (g_count[e] + 63) & ~63;
            g_cursor[e] = 0;
        }
        g_padOff[NE] = off;
        g_Mtot = off;
    }
}

// ---------------- scatter rows into expert-grouped assignment list ----------------
__global__ __launch_bounds__(128) void scatter_kernel() {
    int b = blockIdx.x * 128 + threadIdx.x;
    if (b >= BATCH) return;
    #pragma unroll
    for (int j = 0; j < 2; j++) {
        int e = g_routeE[2 * b + j];
        int pos = g_padOff[e] + atomicAdd(&g_cursor[e], 1);
        g_assignRow[pos] = b;
        g_assignW[pos]   = g_routeW[2 * b + j];
    }
}

// ---------------- GEMM1: H = relu(X[rows] @ W1[e] + b1[e])  (K=2048, N=512) ----------------
__global__ __launch_bounds__(256) void gemm1_kernel(
    const float* __restrict__ x, const float* __restrict__ W1, const float* __restrict__ b1)
{
    int m0 = blockIdx.y * 64;
    if (m0 >= g_Mtot) return;
    int e = 0;
    #pragma unroll
    for (int i = 1; i < NE; i++) if (m0 >= g_padOff[i]) e = i;

    __shared__ float As[16][64];
    __shared__ float Bs[16][64];
    __shared__ int   rowIdx[64];

    int tid = threadIdx.x;
    if (tid < 64) {
        int r = g_assignRow[m0 + tid];
        rowIdx[tid] = (r < 0) ? 0 : r;   // pads compute garbage, discarded via w=0
    }
    __syncthreads();

    int tx = tid & 15, ty = tid >> 4;
    int n0 = blockIdx.x * 64;
    const float* Wb = W1 + (size_t)e * DIM * PP;
    int la_row = tid >> 2;
    int la_k   = (tid & 3) << 2;
    int lb_k   = tid >> 4;
    int lb_n   = (tid & 15) << 2;
    const float* aBase = x + (size_t)rowIdx[la_row] * DIM + la_k;
    const float* bBase = Wb + (size_t)lb_k * PP + n0 + lb_n;

    float acc[4][4] = {};
    float4 aR = *(const float4*)aBase;
    float4 bR = *(const float4*)bBase;

    for (int k0 = 0; k0 < DIM; k0 += 16) {
        As[la_k + 0][la_row] = aR.x;
        As[la_k + 1][la_row] = aR.y;
        As[la_k + 2][la_row] = aR.z;
        As[la_k + 3][la_row] = aR.w;
        *(float4*)&Bs[lb_k][lb_n] = bR;
        __syncthreads();
        int kn = k0 + 16;
        if (kn < DIM) {
            aR = *(const float4*)(aBase + kn);
            bR = *(const float4*)(bBase + (size_t)kn * PP);
        }
        #pragma unroll
        for (int kk = 0; kk < 16; kk++) {
            float4 a = *(const float4*)&As[kk][ty << 2];
            float4 b = *(const float4*)&Bs[kk][tx << 2];
            float av[4] = {a.x, a.y, a.z, a.w};
            float bv[4] = {b.x, b.y, b.z, b.w};
            #pragma unroll
            for (int i = 0; i < 4; i++)
                #pragma unroll
                for (int j = 0; j < 4; j++)
                    acc[i][j] = fmaf(av[i], bv[j], acc[i][j]);
        }
        __syncthreads();
    }

    int colb = n0 + (tx << 2);
    float4 bb = *(const float4*)&b1[(size_t)e * PP + colb];
    #pragma unroll
    for (int i = 0; i < 4; i++) {
        int m = m0 + (ty << 2) + i;
        float4 o;
        o.x = fmaxf(acc[i][0] + bb.x, 0.f);
        o.y = fmaxf(acc[i][1] + bb.y, 0.f);
        o.z = fmaxf(acc[i][2] + bb.z, 0.f);
        o.w = fmaxf(acc[i][3] + bb.w, 0.f);
        *(float4*)&g_H[(size_t)m * PP + colb] = o;
    }
}

// ---------------- GEMM2: out[row] += w * (H @ W2[e] + b2[e])  (K=512, N=2048) ----------------
__global__ __launch_bounds__(256) void gemm2_kernel(
    const float* __restrict__ W2, const float* __restrict__ b2, float* __restrict__ out)
{
    int m0 = blockIdx.y * 64;
    if (m0 >= g_Mtot) return;
    int e = 0;
    #pragma unroll
    for (int i = 1; i < NE; i++) if (m0 >= g_padOff[i]) e = i;

    __shared__ float As[16][64];
    __shared__ float Bs[16][64];
    __shared__ int   rowR[64];
    __shared__ float wR[64];

    int tid = threadIdx.x;
    if (tid < 64) {
        rowR[tid] = g_assignRow[m0 + tid];
        wR[tid]   = g_assignW[m0 + tid];
    }
    __syncthreads();

    int tx = tid & 15, ty = tid >> 4;
    int n0 = blockIdx.x * 64;
    const float* Wb = W2 + (size_t)e * PP * DIM;
    int la_row = tid >> 2;
    int la_k   = (tid & 3) << 2;
    int lb_k   = tid >> 4;
    int lb_n   = (tid & 15) << 2;
    const float* aBase = g_H + (size_t)(m0 + la_row) * PP + la_k;
    const float* bBase = Wb + (size_t)lb_k * DIM + n0 + lb_n;

    float acc[4][4] = {};
    float4 aR = *(const float4*)aBase;
    float4 bR = *(const float4*)bBase;

    for (int k0 = 0; k0 < PP; k0 += 16) {
        As[la_k + 0][la_row] = aR.x;
        As[la_k + 1][la_row] = aR.y;
        As[la_k + 2][la_row] = aR.z;
        As[la_k + 3][la_row] = aR.w;
        *(float4*)&Bs[lb_k][lb_n] = bR;
        __syncthreads();
        int kn = k0 + 16;
        if (kn < PP) {
            aR = *(const float4*)(aBase + kn);
            bR = *(const float4*)(bBase + (size_t)kn * DIM);
        }
        #pragma unroll
        for (int kk = 0; kk < 16; kk++) {
            float4 a = *(const float4*)&As[kk][ty << 2];
            float4 b = *(const float4*)&Bs[kk][tx << 2];
            float av[4] = {a.x, a.y, a.z, a.w};
            float bv[4] = {b.x, b.y, b.z, b.w};
            #pragma unroll
            for (int i = 0; i < 4; i++)
                #pragma unroll
                for (int j = 0; j < 4; j++)
                    acc[i][j] = fmaf(av[i], bv[j], acc[i][j]);
        }
        __syncthreads();
    }

    int colb = n0 + (tx << 2);
    float4 bb = *(const float4*)&b2[(size_t)e * DIM + colb];
    float bv2[4] = {bb.x, bb.y, bb.z, bb.w};
    #pragma unroll
    for (int i = 0; i < 4; i++) {
        int r = rowR[(ty << 2) + i];
        if (r < 0) continue;                      // padding slot
        float w = wR[(ty << 2) + i];
        float* orow = out + (size_t)r * DIM + colb;
        #pragma unroll
        for (int j = 0; j < 4; j++)
            atomicAdd(&orow[j], w * (acc[i][j] + bv2[j]));
    }
}

// ---------------- launch ----------------
extern "C" void kernel_launch(void* const* d_in, const int* in_sizes, int n_in,
                              void* d_out, int out_size)
{
    const float* x   = (const float*)d_in[0];
    const float* Wg  = (const float*)d_in[1];
    const float* bg  = (const float*)d_in[2];
    const float* Wp  = (const float*)d_in[3];
    const float* bp  = (const float*)d_in[4];
    const float* Wgg = (const float*)d_in[5];
    const float* bgg = (const float*)d_in[6];
    const float* W1  = (const float*)d_in[7];
    const float* b1  = (const float*)d_in[8];
    const float* W2  = (const float*)d_in[9];
    const float* b2  = (const float*)d_in[10];
    float* out = (float*)d_out;

    init_kernel<<<16384, 256>>>((float4*)out);
    route_kernel<<<BATCH, 1024>>>(x, Wg, bg, Wp, bp, Wgg, bgg);
    scan_kernel<<<1, 32>>>();
    scatter_kernel<<<(BATCH + 127) / 128, 128>>>();
    gemm1_kernel<<<dim3(PP / 64, MT_MAX), 256>>>(x, W1, b1);
    gemm2_kernel<<<dim3(DIM / 64, MT_MAX), 256>>>(W2, b2, out);
}

// round 7
// speedup vs baseline: 1.4877x; 1.4877x over previous
#include <cuda_runtime.h>
#include <cuda_bf16.h>
#include <mma.h>
#include <math.h>
#include <stdint.h>

using namespace nvcuda;

// ---------------- problem constants ----------------
#define BATCH 8192
#define DIM   2048
#define NE    8
#define NG    4
#define PP    512
#define HH    192
#define CAP   17408          // max padded assignments (128-row tiles)
#define MTILES 136           // CAP/128
#define KCH   32             // K elems per smem chunk

// ---------------- device scratch (total ~36 MB — below proven-safe R2 level) ----------------
__device__ int   g_count[NE];
__device__ int   g_cursor[NE];
__device__ int   g_padOff[NE + 1];
__device__ int   g_Mtot;
__device__ int   g_routeE[2 * BATCH];
__device__ float g_routeW[2 * BATCH];
__device__ __align__(1024) int   g_assignRow[CAP];
__device__ __align__(1024) float g_assignW[CAP];
__device__ __align__(1024) __nv_bfloat16 g_Hhi[(size_t)CAP * PP];
__device__ __align__(1024) __nv_bfloat16 g_Hlo[(size_t)CAP * PP];

// ---------------- smem layout (union of staging phase / epilogue phase) ----------------
#define SA_HI  0        // 128 x 40 bf16 = 10240 B
#define SA_LO  10240    // 128 x 40 bf16
#define SB_HI  20480    // 32 x 72 bf16 = 4608 B
#define SB_LO  25088    // 32 x 72 bf16  (end 29696)
#define CBUF_LD 68      // epilogue float buffer 128 x 68 x 4 = 34816 B
#define SMEM_BYTES 34816

// ---------------- init: zero output + scratch ----------------
__global__ __launch_bounds__(256) void init_kernel(float4* __restrict__ out4) {
    int i = blockIdx.x * 256 + threadIdx.x;           // 16384 x 256 = BATCH*DIM/4
    if (i < (BATCH * DIM) / 4) out4[i] = make_float4(0.f, 0.f, 0.f, 0.f);
    if (i < CAP) { g_assignRow[i] = -1; g_assignW[i] = 0.f; }
    if (i < NE)  { g_count[i] = 0; g_cursor[i] = 0; }
}

// ---------------- routing (exactness-critical; identical to passing round-2) ----------------
__global__ __launch_bounds__(1024) void route_kernel(
    const float* __restrict__ x,
    const float* __restrict__ Wg, const float* __restrict__ bg,
    const float* __restrict__ Wp, const float* __restrict__ bp,
    const float* __restrict__ Wgg, const float* __restrict__ bgg)
{
    __shared__ float  warpSum[32];
    __shared__ double dWarp[32];
    __shared__ float  sh_qm;
    int b = blockIdx.x, tid = threadIdx.x;

    const float2* xr = (const float2*)(x + (size_t)b * DIM);
    float2 v = xr[tid];
    float acc = v.x + v.y;
    #pragma unroll
    for (int o = 16; o; o >>= 1) acc += __shfl_down_sync(0xffffffffu, acc, o);
    if ((tid & 31) == 0) warpSum[tid >> 5] = acc;
    __syncthreads();
    if (tid < 32) {
        float a2 = warpSum[tid];
        #pragma unroll
        for (int o = 16; o; o >>= 1) a2 += __shfl_down_sync(0xffffffffu, a2, o);
        if (tid == 0) sh_qm = a2 * (1.0f / 2048.0f);
    }
    __syncthreads();
    float qm = sh_qm;

    double tr = 0.0;
    if (tid < HH) {
        float ang = __fmul_rn(qm, (float)(7 * (tid + 1)));
        double da = (double)ang;
        tr = cos(da) + sin(da);
    }
    #pragma unroll
    for (int o = 16; o; o >>= 1) tr += __shfl_down_sync(0xffffffffu, tr, o);
    if ((tid & 31) == 0) dWarp[tid >> 5] = tr;
    __syncthreads();

    if (tid == 0) {
        double t = 0.0;
        #pragma unroll
        for (int i = 0; i < 32; i++) t += dWarp[i];
        double m = t / 384.0;
        const double c = 0.015625;   // KTOP/D: LIF spike rate is exactly constant

        double l[NE]; double mx = -1e300;
        #pragma unroll
        for (int e = 0; e < NE; e++) {
            int g = e & (NG - 1);
            double v2 = (m * (double)Wg[e] + c * (double)Wg[NE + e] + (double)bg[e])
                      - 0.1 * (m * (double)Wp[e] + c * (double)Wp[NE + e] + (double)bp[e])
                      + (m * (double)Wgg[g] + c * (double)Wgg[NG + g] + (double)bgg[g]);
            l[e] = v2; mx = fmax(mx, v2);
        }
        double sf[NE], Z = 0.0;
        #pragma unroll
        for (int e = 0; e < NE; e++) { sf[e] = exp(l[e] - mx); Z += sf[e]; }
        int e0 = 0;
        #pragma unroll
        for (int e = 1; e < NE; e++) if (sf[e] > sf[e0]) e0 = e;
        int e1 = (e0 == 0) ? 1 : 0;
        #pragma unroll
        for (int e = 0; e < NE; e++) if (e != e0 && sf[e] > sf[e1]) e1 = e;
        double s0 = sf[e0] / Z, s1 = sf[e1] / Z;
        double den = s0 + s1 + 1e-9;

        g_routeE[2 * b] = e0; g_routeE[2 * b + 1] = e1;
        g_routeW[2 * b] = (float)(s0 / den); g_routeW[2 * b + 1] = (float)(s1 / den);
        atomicAdd(&g_count[e0], 1);
        atomicAdd(&g_count[e1], 1);
    }
}

__global__ void scan_kernel() {
    if (blockIdx.x == 0 && threadIdx.x == 0) {
        int off = 0;
        #pragma unroll
        for (int e = 0; e < NE; e++) {
            g_padOff[e] = off;
            off += (g_count[e] + 127) & ~127;
            g_cursor[e] = 0;
        }
        g_padOff[NE] = off;
        g_Mtot = off;
    }
}

__global__ __launch_bounds__(128) void scatter_kernel() {
    int b = blockIdx.x * 128 + threadIdx.x;
    if (b >= BATCH) return;
    #pragma unroll
    for (int j = 0; j < 2; j++) {
        int e = g_routeE[2 * b + j];
        int pos = g_padOff[e] + atomicAdd(&g_cursor[e], 1);
        g_assignRow[pos] = b;
        g_assignW[pos]   = g_routeW[2 * b + j];
    }
}

// ---------------- helpers ----------------
__device__ __forceinline__ void split4_store(__nv_bfloat16* dhi, __nv_bfloat16* dlo, float4 v) {
    float vv[4] = {v.x, v.y, v.z, v.w};
    #pragma unroll
    for (int t = 0; t < 4; t++) {
        __nv_bfloat16 h = __float2bfloat16_rn(vv[t]);
        dhi[t] = h;
        dlo[t] = __float2bfloat16_rn(vv[t] - __bfloat162float(h));
    }
}

// =====================================================================
// WMMA GEMM: CTA tile 128x64, 8 warps (warp 32x32 = 2x2 wmma16x16x16),
// K-chunk 32, split-3 bf16 (hh + hl + lh), fp32 accumulate.
// fp32 inputs split in-register during staging — NO prep arrays needed.
// =====================================================================

// ---------------- GEMM1: H = relu(X[rows] @ W1[e] + b1[e]); W1 is [k][n] row-major ----------------
__global__ __launch_bounds__(256) void wmma_gemm1(
    const float* __restrict__ x, const float* __restrict__ W1, const float* __restrict__ b1)
{
    __shared__ __align__(16) char smem[SMEM_BYTES];
    __shared__ int s_row[128];

    int m0 = blockIdx.y * 128;
    if (m0 >= g_Mtot) return;
    int e = 0;
    #pragma unroll
    for (int i = 1; i < NE; i++) if (m0 >= g_padOff[i]) e = i;
    int n0 = blockIdx.x * 64;
    int tid = threadIdx.x, wid = tid >> 5;
    int wm = wid & 3, wn = wid >> 2;

    if (tid < 128) { int r = g_assignRow[m0 + tid]; s_row[tid] = r < 0 ? 0 : r; }
    __syncthreads();

    __nv_bfloat16* sAhi = (__nv_bfloat16*)(smem + SA_HI);
    __nv_bfloat16* sAlo = (__nv_bfloat16*)(smem + SA_LO);
    __nv_bfloat16* sBhi = (__nv_bfloat16*)(smem + SB_HI);
    __nv_bfloat16* sBlo = (__nv_bfloat16*)(smem + SB_LO);
    const float* Wb = W1 + (size_t)e * DIM * PP;

    wmma::fragment<wmma::accumulator, 16, 16, 16, float> acc[2][2];
    #pragma unroll
    for (int mi = 0; mi < 2; mi++)
        #pragma unroll
        for (int ni = 0; ni < 2; ni++)
            wmma::fill_fragment(acc[mi][ni], 0.0f);

    for (int k0 = 0; k0 < DIM; k0 += KCH) {
        // A: 128 rows x 32 k fp32, gathered; split to bf16 hi/lo
        #pragma unroll
        for (int j = 0; j < 4; j++) {
            int i = tid + 256 * j;                 // 0..1023
            int row = i >> 3, q = i & 7;           // 8 float4 per row
            float4 v = *(const float4*)(x + (size_t)s_row[row] * DIM + k0 + q * 4);
            split4_store(&sAhi[row * 40 + q * 4], &sAlo[row * 40 + q * 4], v);
        }
        // B: 32 k-rows x 64 n fp32 from W1[k][n]; split
        #pragma unroll
        for (int j = 0; j < 2; j++) {
            int i = tid + 256 * j;                 // 0..511
            int row = i >> 4, q = i & 15;          // 16 float4 per row
            float4 v = *(const float4*)(Wb + (size_t)(k0 + row) * PP + n0 + q * 4);
            split4_store(&sBhi[row * 72 + q * 4], &sBlo[row * 72 + q * 4], v);
        }
        __syncthreads();

        #pragma unroll
        for (int ks = 0; ks < 2; ks++) {
            wmma::fragment<wmma::matrix_a, 16, 16, 16, __nv_bfloat16, wmma::row_major> ah[2], al[2];
            wmma::fragment<wmma::matrix_b, 16, 16, 16, __nv_bfloat16, wmma::row_major> bh[2], bl[2];
            #pragma unroll
            for (int mi = 0; mi < 2; mi++) {
                wmma::load_matrix_sync(ah[mi], &sAhi[(wm * 32 + mi * 16) * 40 + ks * 16], 40);
                wmma::load_matrix_sync(al[mi], &sAlo[(wm * 32 + mi * 16) * 40 + ks * 16], 40);
            }
            #pragma unroll
            for (int ni = 0; ni < 2; ni++) {
                wmma::load_matrix_sync(bh[ni], &sBhi[(ks * 16) * 72 + wn * 32 + ni * 16], 72);
                wmma::load_matrix_sync(bl[ni], &sBlo[(ks * 16) * 72 + wn * 32 + ni * 16], 72);
            }
            #pragma unroll
            for (int mi = 0; mi < 2; mi++)
                #pragma unroll
                for (int ni = 0; ni < 2; ni++) {
                    wmma::mma_sync(acc[mi][ni], ah[mi], bh[ni], acc[mi][ni]);
                    wmma::mma_sync(acc[mi][ni], ah[mi], bl[ni], acc[mi][ni]);
                    wmma::mma_sync(acc[mi][ni], al[mi], bh[ni], acc[mi][ni]);
                }
        }
        __syncthreads();
    }

    // epilogue: acc -> smem float buffer -> bias+relu+split -> g_Hhi/Hlo
    float* Cbuf = (float*)smem;
    #pragma unroll
    for (int mi = 0; mi < 2; mi++)
        #pragma unroll
        for (int ni = 0; ni < 2; ni++)
            wmma::store_matrix_sync(&Cbuf[(wm * 32 + mi * 16) * CBUF_LD + wn * 32 + ni * 16],
                                    acc[mi][ni], CBUF_LD, wmma::mem_row_major);
    __syncthreads();

    const float* bb = b1 + e * PP;
    #pragma unroll
    for (int j = 0; j < 16; j++) {
        int idx = tid + 256 * j;                   // 0..4095 = 128 rows x 32 col-pairs
        int r = idx >> 5, c = (idx & 31) * 2;
        int col = n0 + c;
        float v0 = fmaxf(Cbuf[r * CBUF_LD + c]     + bb[col],     0.f);
        float v1 = fmaxf(Cbuf[r * CBUF_LD + c + 1] + bb[col + 1], 0.f);
        __nv_bfloat16 h0 = __float2bfloat16_rn(v0), h1 = __float2bfloat16_rn(v1);
        __nv_bfloat162 hh; hh.x = h0; hh.y = h1;
        *(__nv_bfloat162*)&g_Hhi[(size_t)(m0 + r) * PP + col] = hh;
        __nv_bfloat162 ll;
        ll.x = __float2bfloat16_rn(v0 - __bfloat162float(h0));
        ll.y = __float2bfloat16_rn(v1 - __bfloat162float(h1));
        *(__nv_bfloat162*)&g_Hlo[(size_t)(m0 + r) * PP + col] = ll;
    }
}

// ---------------- GEMM2: out[row] += w * (H @ W2[e] + b2[e]); W2 is [k][n] row-major ----------------
__global__ __launch_bounds__(256) void wmma_gemm2(
    const float* __restrict__ W2, const float* __restrict__ b2, float* __restrict__ out)
{
    __shared__ __align__(16) char smem[SMEM_BYTES];
    __shared__ int   s_rowR[128];
    __shared__ float s_w[128];

    int m0 = blockIdx.y * 128;
    if (m0 >= g_Mtot) return;
    int e = 0;
    #pragma unroll
    for (int i = 1; i < NE; i++) if (m0 >= g_padOff[i]) e = i;
    int n0 = blockIdx.x * 64;
    int tid = threadIdx.x, wid = tid >> 5;
    int wm = wid & 3, wn = wid >> 2;

    if (tid < 128) { s_rowR[tid] = g_assignRow[m0 + tid]; s_w[tid] = g_assignW[m0 + tid]; }
    __syncthreads();

    __nv_bfloat16* sAhi = (__nv_bfloat16*)(smem + SA_HI);
    __nv_bfloat16* sAlo = (__nv_bfloat16*)(smem + SA_LO);
    __nv_bfloat16* sBhi = (__nv_bfloat16*)(smem + SB_HI);
    __nv_bfloat16* sBlo = (__nv_bfloat16*)(smem + SB_LO);
    const float* Wb = W2 + (size_t)e * PP * DIM;

    wmma::fragment<wmma::accumulator, 16, 16, 16, float> acc[2][2];
    #pragma unroll
    for (int mi = 0; mi < 2; mi++)
        #pragma unroll
        for (int ni = 0; ni < 2; ni++)
            wmma::fill_fragment(acc[mi][ni], 0.0f);

    for (int k0 = 0; k0 < PP; k0 += KCH) {
        // A: 128 rows x 32 k, already-split bf16 from g_Hhi/Hlo
        #pragma unroll
        for (int j = 0; j < 2; j++) {
            int i = tid + 256 * j;                 // 0..511
            int row = i >> 2, q = i & 3;           // 4 uint4 per row (32 bf16)
            size_t go = (size_t)(m0 + row) * PP + k0 + q * 8;
            *(uint4*)&sAhi[row * 40 + q * 8] = *(const uint4*)(g_Hhi + go);
            *(uint4*)&sAlo[row * 40 + q * 8] = *(const uint4*)(g_Hlo + go);
        }
        // B: 32 k-rows x 64 n fp32 from W2[k][n]; split
        #pragma unroll
        for (int j = 0; j < 2; j++) {
            int i = tid + 256 * j;
            int row = i >> 4, q = i & 15;
            float4 v = *(const float4*)(Wb + (size_t)(k0 + row) * DIM + n0 + q * 4);
            split4_store(&sBhi[row * 72 + q * 4], &sBlo[row * 72 + q * 4], v);
        }
        __syncthreads();

        #pragma unroll
        for (int ks = 0; ks < 2; ks++) {
            wmma::fragment<wmma::matrix_a, 16, 16, 16, __nv_bfloat16, wmma::row_major> ah[2], al[2];
            wmma::fragment<wmma::matrix_b, 16, 16, 16, __nv_bfloat16, wmma::row_major> bh[2], bl[2];
            #pragma unroll
            for (int mi = 0; mi < 2; mi++) {
                wmma::load_matrix_sync(ah[mi], &sAhi[(wm * 32 + mi * 16) * 40 + ks * 16], 40);
                wmma::load_matrix_sync(al[mi], &sAlo[(wm * 32 + mi * 16) * 40 + ks * 16], 40);
            }
            #pragma unroll
            for (int ni = 0; ni < 2; ni++) {
                wmma::load_matrix_sync(bh[ni], &sBhi[(ks * 16) * 72 + wn * 32 + ni * 16], 72);
                wmma::load_matrix_sync(bl[ni], &sBlo[(ks * 16) * 72 + wn * 32 + ni * 16], 72);
            }
            #pragma unroll
            for (int mi = 0; mi < 2; mi++)
                #pragma unroll
                for (int ni = 0; ni < 2; ni++) {
                    wmma::mma_sync(acc[mi][ni], ah[mi], bh[ni], acc[mi][ni]);
                    wmma::mma_sync(acc[mi][ni], ah[mi], bl[ni], acc[mi][ni]);
                    wmma::mma_sync(acc[mi][ni], al[mi], bh[ni], acc[mi][ni]);
                }
        }
        __syncthreads();
    }

    // epilogue: acc -> smem -> gated atomicAdd into out (2 commutative adds/element)
    float* Cbuf = (float*)smem;
    #pragma unroll
    for (int mi = 0; mi < 2; mi++)
        #pragma unroll
        for (int ni = 0; ni < 2; ni++)
            wmma::store_matrix_sync(&Cbuf[(wm * 32 + mi * 16) * CBUF_LD + wn * 32 + ni * 16],
                                    acc[mi][ni], CBUF_LD, wmma::mem_row_major);
    __syncthreads();

    const float* bb = b2 + e * DIM;
    #pragma unroll
    for (int j = 0; j < 16; j++) {
        int idx = tid + 256 * j;                   // 128 rows x 32 col-pairs
        int r = idx >> 5, c = (idx & 31) * 2;
        int row = s_rowR[r];
        if (row < 0) continue;                     // padding slot
        float w = s_w[r];
        int col = n0 + c;
        float* orow = out + (size_t)row * DIM;
        atomicAdd(&orow[col],     w * (Cbuf[r * CBUF_LD + c]     + bb[col]));
        atomicAdd(&orow[col + 1], w * (Cbuf[r * CBUF_LD + c + 1] + bb[col + 1]));
    }
}

// ---------------- launch ----------------
extern "C" void kernel_launch(void* const* d_in, const int* in_sizes, int n_in,
                              void* d_out, int out_size)
{
    const float* x   = (const float*)d_in[0];
    const float* Wg  = (const float*)d_in[1];
    const float* bg  = (const float*)d_in[2];
    const float* Wp  = (const float*)d_in[3];
    const float* bp  = (const float*)d_in[4];
    const float* Wgg = (const float*)d_in[5];
    const float* bgg = (const float*)d_in[6];
    const float* W1  = (const float*)d_in[7];
    const float* b1  = (const float*)d_in[8];
    const float* W2  = (const float*)d_in[9];
    const float* b2  = (const float*)d_in[10];
    float* out = (float*)d_out;

    init_kernel<<<16384, 256>>>((float4*)out);
    route_kernel<<<BATCH, 1024>>>(x, Wg, bg, Wp, bp, Wgg, bgg);
    scan_kernel<<<1, 32>>>();
    scatter_kernel<<<(BATCH + 127) / 128, 128>>>();
    wmma_gemm1<<<dim3(PP / 64, MTILES), 256>>>(x, W1, b1);
    wmma_gemm2<<<dim3(DIM / 64, MTILES), 256>>>(W2, b2, out);
}

// round 9
// speedup vs baseline: 1.5671x; 1.0533x over previous
#include <cuda_runtime.h>
#include <cuda_bf16.h>
#include <mma.h>
#include <math.h>
#include <stdint.h>

using namespace nvcuda;

// ---------------- problem constants ----------------
#define BATCH 8192
#define DIM   2048
#define NE    8
#define NG    4
#define PP    512
#define HH    192
#define CAP   17408          // max padded assignments (128-row tiles)
#define MTILES 136           // CAP/128
#define KCH   16             // K elems per smem chunk (2-stage double buffer)

// ---------------- device scratch (~36 MB total — proven-safe envelope) ----------------
__device__ int   g_count[NE];
__device__ int   g_cursor[NE];
__device__ int   g_padOff[NE + 1];
__device__ int   g_Mtot;
__device__ int   g_routeE[2 * BATCH];
__device__ float g_routeW[2 * BATCH];
__device__ __align__(1024) int   g_assignRow[CAP];
__device__ __align__(1024) float g_assignW[CAP];
__device__ __align__(1024) __nv_bfloat16 g_Hhi[(size_t)CAP * PP];
__device__ __align__(1024) __nv_bfloat16 g_Hlo[(size_t)CAP * PP];

// ---------------- smem layout ----------------
// stage s (s=0,1), stage size 16896 B:
//   A hi: 128 x 24 bf16 = 6144 B   | A lo: 6144 B
//   B hi:  16 x 72 bf16 = 2304 B   | B lo: 2304 B
// epilogue float buffer (union): 128 x 68 x 4 = 34816 B
#define STAGE_SZ 16896
#define SAH(s) ((s) * STAGE_SZ)
#define SAL(s) ((s) * STAGE_SZ + 6144)
#define SBH(s) ((s) * STAGE_SZ + 12288)
#define SBL(s) ((s) * STAGE_SZ + 14592)
#define CBUF_LD 68
#define SMEM_BYTES 34816

// ---------------- init: zero output + scratch ----------------
__global__ __launch_bounds__(256) void init_kernel(float4* __restrict__ out4) {
    int i = blockIdx.x * 256 + threadIdx.x;           // 16384 x 256 = BATCH*DIM/4
    if (i < (BATCH * DIM) / 4) out4[i] = make_float4(0.f, 0.f, 0.f, 0.f);
    if (i < CAP) { g_assignRow[i] = -1; g_assignW[i] = 0.f; }
    if (i < NE)  { g_count[i] = 0; g_cursor[i] = 0; }
}

// ---------------- routing (exactness-critical; identical to passing rounds) ----------------
__global__ __launch_bounds__(1024) void route_kernel(
    const float* __restrict__ x,
    const float* __restrict__ Wg, const float* __restrict__ bg,
    const float* __restrict__ Wp, const float* __restrict__ bp,
    const float* __restrict__ Wgg, const float* __restrict__ bgg)
{
    __shared__ float  warpSum[32];
    __shared__ double dWarp[32];
    __shared__ float  sh_qm;
    int b = blockIdx.x, tid = threadIdx.x;

    const float2* xr = (const float2*)(x + (size_t)b * DIM);
    float2 v = xr[tid];
    float acc = v.x + v.y;
    #pragma unroll
    for (int o = 16; o; o >>= 1) acc += __shfl_down_sync(0xffffffffu, acc, o);
    if ((tid & 31) == 0) warpSum[tid >> 5] = acc;
    __syncthreads();
    if (tid < 32) {
        float a2 = warpSum[tid];
        #pragma unroll
        for (int o = 16; o; o >>= 1) a2 += __shfl_down_sync(0xffffffffu, a2, o);
        if (tid == 0) sh_qm = a2 * (1.0f / 2048.0f);
    }
    __syncthreads();
    float qm = sh_qm;

    double tr = 0.0;
    if (tid < HH) {
        float ang = __fmul_rn(qm, (float)(7 * (tid + 1)));
        double da = (double)ang;
        tr = cos(da) + sin(da);
    }
    #pragma unroll
    for (int o = 16; o; o >>= 1) tr += __shfl_down_sync(0xffffffffu, tr, o);
    if ((tid & 31) == 0) dWarp[tid >> 5] = tr;
    __syncthreads();

    if (tid == 0) {
        double t = 0.0;
        #pragma unroll
        for (int i = 0; i < 32; i++) t += dWarp[i];
        double m = t / 384.0;
        const double c = 0.015625;   // KTOP/D: LIF spike rate is exactly constant

        double l[NE]; double mx = -1e300;
        #pragma unroll
        for (int e = 0; e < NE; e++) {
            int g = e & (NG - 1);
            double v2 = (m * (double)Wg[e] + c * (double)Wg[NE + e] + (double)bg[e])
                      - 0.1 * (m * (double)Wp[e] + c * (double)Wp[NE + e] + (double)bp[e])
                      + (m * (double)Wgg[g] + c * (double)Wgg[NG + g] + (double)bgg[g]);
            l[e] = v2; mx = fmax(mx, v2);
        }
        double sf[NE], Z = 0.0;
        #pragma unroll
        for (int e = 0; e < NE; e++) { sf[e] = exp(l[e] - mx); Z += sf[e]; }
        int e0 = 0;
        #pragma unroll
        for (int e = 1; e < NE; e++) if (sf[e] > sf[e0]) e0 = e;
        int e1 = (e0 == 0) ? 1 : 0;
        #pragma unroll
        for (int e = 0; e < NE; e++) if (e != e0 && sf[e] > sf[e1]) e1 = e;
        double s0 = sf[e0] / Z, s1 = sf[e1] / Z;
        double den = s0 + s1 + 1e-9;

        g_routeE[2 * b] = e0; g_routeE[2 * b + 1] = e1;
        g_routeW[2 * b] = (float)(s0 / den); g_routeW[2 * b + 1] = (float)(s1 / den);
        atomicAdd(&g_count[e0], 1);
        atomicAdd(&g_count[e1], 1);
    }
}

__global__ void scan_kernel() {
    if (blockIdx.x == 0 && threadIdx.x == 0) {
        int off = 0;
        #pragma unroll
        for (int e = 0; e < NE; e++) {
            g_padOff[e] = off;
            off += (g_count[e] + 127) & ~127;
            g_cursor[e] = 0;
        }
        g_padOff[NE] = off;
        g_Mtot = off;
    }
}

__global__ __launch_bounds__(128) void scatter_kernel() {
    int b = blockIdx.x * 128 + threadIdx.x;
    if (b >= BATCH) return;
    #pragma unroll
    for (int j = 0; j < 2; j++) {
        int e = g_routeE[2 * b + j];
        int pos = g_padOff[e] + atomicAdd(&g_cursor[e], 1);
        g_assignRow[pos] = b;
        g_assignW[pos]   = g_routeW[2 * b + j];
    }
}

// ---------------- helpers ----------------
__device__ __forceinline__ void split4(float4 v, uint2& hi, uint2& lo) {
    __nv_bfloat162 h01 = __floats2bfloat162_rn(v.x, v.y);
    __nv_bfloat162 h23 = __floats2bfloat162_rn(v.z, v.w);
    hi.x = *(uint32_t*)&h01;
    hi.y = *(uint32_t*)&h23;
    __nv_bfloat162 l01 = __floats2bfloat162_rn(v.x - __bfloat162float(h01.x),
                                               v.y - __bfloat162float(h01.y));
    __nv_bfloat162 l23 = __floats2bfloat162_rn(v.z - __bfloat162float(h23.x),
                                               v.w - __bfloat162float(h23.y));
    lo.x = *(uint32_t*)&l01;
    lo.y = *(uint32_t*)&l23;
}

// =====================================================================
// WMMA GEMM: CTA tile 128x64, 8 warps (warp 32x32 = 2x2 wmma16x16x16),
// KCH=16, 2-stage double buffer (1 sync/iter) + register prefetch,
// split-3 bf16 (hh + hl + lh), fp32 accumulate.
// =====================================================================

// ---------------- GEMM1: H = relu(X[rows] @ W1[e] + b1[e]); W1 is [k][n] ----------------
__global__ __launch_bounds__(256, 2) void wmma_gemm1(
    const float* __restrict__ x, const float* __restrict__ W1, const float* __restrict__ b1)
{
    __shared__ __align__(16) char smem[SMEM_BYTES];
    __shared__ int s_row[128];

    int m0 = blockIdx.y * 128;
    if (m0 >= g_Mtot) return;
    int e = 0;
    #pragma unroll
    for (int i = 1; i < NE; i++) if (m0 >= g_padOff[i]) e = i;
    int n0 = blockIdx.x * 64;
    int tid = threadIdx.x, wid = tid >> 5;
    int wm = wid & 3, wn = wid >> 2;

    if (tid < 128) { int r = g_assignRow[m0 + tid]; s_row[tid] = r < 0 ? 0 : r; }
    __syncthreads();

    const float* Wb = W1 + (size_t)e * DIM * PP;

    // staging geometry: A 128x16 fp32 = 512 float4 (2/thread), B 16x64 = 256 float4 (1/thread)
    int arow = tid >> 2, aq = tid & 3;         // rows arow, arow+64; k-offset aq*4
    int brow = tid >> 4, bq = tid & 15;        // k-row brow; n-offset bq*4
    const float* aP0 = x + (size_t)s_row[arow] * DIM + aq * 4;
    const float* aP1 = x + (size_t)s_row[arow + 64] * DIM + aq * 4;
    const float* bP  = Wb + (size_t)brow * PP + n0 + bq * 4;

    float4 ra0 = *(const float4*)aP0;
    float4 ra1 = *(const float4*)aP1;
    float4 rb  = *(const float4*)bP;

    wmma::fragment<wmma::accumulator, 16, 16, 16, float> acc[2][2];
    #pragma unroll
    for (int mi = 0; mi < 2; mi++)
        #pragma unroll
        for (int ni = 0; ni < 2; ni++)
            wmma::fill_fragment(acc[mi][ni], 0.0f);

    const int NK = DIM / KCH;   // 128
    for (int k = 0; k < NK; k++) {
        int s = k & 1;
        __nv_bfloat16* sAhi = (__nv_bfloat16*)(smem + SAH(s));
        __nv_bfloat16* sAlo = (__nv_bfloat16*)(smem + SAL(s));
        __nv_bfloat16* sBhi = (__nv_bfloat16*)(smem + SBH(s));
        __nv_bfloat16* sBlo = (__nv_bfloat16*)(smem + SBL(s));

        {   // STS from prefetched regs
            uint2 hi, lo;
            split4(ra0, hi, lo);
            *(uint2*)&sAhi[arow * 24 + aq * 4] = hi;
            *(uint2*)&sAlo[arow * 24 + aq * 4] = lo;
            split4(ra1, hi, lo);
            *(uint2*)&sAhi[(arow + 64) * 24 + aq * 4] = hi;
            *(uint2*)&sAlo[(arow + 64) * 24 + aq * 4] = lo;
            split4(rb, hi, lo);
            *(uint2*)&sBhi[brow * 72 + bq * 4] = hi;
            *(uint2*)&sBlo[brow * 72 + bq * 4] = lo;
        }
        __syncthreads();

        if (k + 1 < NK) {       // prefetch next chunk; latency hidden by mma below
            int k0 = (k + 1) * KCH;
            ra0 = *(const float4*)(aP0 + k0);
            ra1 = *(const float4*)(aP1 + k0);
            rb  = *(const float4*)(bP + (size_t)k0 * PP);
        }

        wmma::fragment<wmma::matrix_a, 16, 16, 16, __nv_bfloat16, wmma::row_major> ah[2], al[2];
        wmma::fragment<wmma::matrix_b, 16, 16, 16, __nv_bfloat16, wmma::row_major> bh[2], bl[2];
        #pragma unroll
        for (int mi = 0; mi < 2; mi++) {
            wmma::load_matrix_sync(ah[mi], &sAhi[(wm * 32 + mi * 16) * 24], 24);
            wmma::load_matrix_sync(al[mi], &sAlo[(wm * 32 + mi * 16) * 24], 24);
        }
        #pragma unroll
        for (int ni = 0; ni < 2; ni++) {
            wmma::load_matrix_sync(bh[ni], &sBhi[wn * 32 + ni * 16], 72);
            wmma::load_matrix_sync(bl[ni], &sBlo[wn * 32 + ni * 16], 72);
        }
        #pragma unroll
        for (int mi = 0; mi < 2; mi++)
            #pragma unroll
            for (int ni = 0; ni < 2; ni++) {
                wmma::mma_sync(acc[mi][ni], ah[mi], bh[ni], acc[mi][ni]);
                wmma::mma_sync(acc[mi][ni], ah[mi], bl[ni], acc[mi][ni]);
                wmma::mma_sync(acc[mi][ni], al[mi], bh[ni], acc[mi][ni]);
            }
        // no second sync: next STS targets the other stage buffer
    }
    __syncthreads();

    // epilogue: acc -> smem float buffer -> bias+relu+split -> g_Hhi/Hlo
    float* Cbuf = (float*)smem;
    #pragma unroll
    for (int mi = 0; mi < 2; mi++)
        #pragma unroll
        for (int ni = 0; ni < 2; ni++)
            wmma::store_matrix_sync(&Cbuf[(wm * 32 + mi * 16) * CBUF_LD + wn * 32 + ni * 16],
                                    acc[mi][ni], CBUF_LD, wmma::mem_row_major);
    __syncthreads();

    const float* bb = b1 + e * PP;
    #pragma unroll
    for (int j = 0; j < 16; j++) {
        int idx = tid + 256 * j;                   // 128 rows x 32 col-pairs
        int r = idx >> 5, c = (idx & 31) * 2;
        int col = n0 + c;
        float v0 = fmaxf(Cbuf[r * CBUF_LD + c]     + bb[col],     0.f);
        float v1 = fmaxf(Cbuf[r * CBUF_LD + c + 1] + bb[col + 1], 0.f);
        __nv_bfloat16 h0 = __float2bfloat16_rn(v0), h1 = __float2bfloat16_rn(v1);
        __nv_bfloat162 hh; hh.x = h0; hh.y = h1;
        *(__nv_bfloat162*)&g_Hhi[(size_t)(m0 + r) * PP + col] = hh;
        __nv_bfloat162 ll;
        ll.x = __float2bfloat16_rn(v0 - __bfloat162float(h0));
        ll.y = __float2bfloat16_rn(v1 - __bfloat162float(h1));
        *(__nv_bfloat162*)&g_Hlo[(size_t)(m0 + r) * PP + col] = ll;
    }
}

// ---------------- GEMM2: out[row] += w * (H @ W2[e] + b2[e]); W2 is [k][n] ----------------
__global__ __launch_bounds__(256, 2) void wmma_gemm2(
    const float* __restrict__ W2, const float* __restrict__ b2, float* __restrict__ out)
{
    __shared__ __align__(16) char smem[SMEM_BYTES];
    __shared__ int   s_rowR[128];
    __shared__ float s_w[128];

    int m0 = blockIdx.y * 128;
    if (m0 >= g_Mtot) return;
    int e = 0;
    #pragma unroll
    for (int i = 1; i < NE; i++) if (m0 >= g_padOff[i]) e = i;
    int n0 = blockIdx.x * 64;
    int tid = threadIdx.x, wid = tid >> 5;
    int wm = wid & 3, wn = wid >> 2;

    if (tid < 128) { s_rowR[tid] = g_assignRow[m0 + tid]; s_w[tid] = g_assignW[m0 + tid]; }
    __syncthreads();

    const float* Wb = W2 + (size_t)e * PP * DIM;

    // A: 128x16 bf16 = 256 uint4 per hi/lo (1/thread); B: 16x64 fp32 = 256 float4 (1/thread)
    int arow = tid >> 1, aq = tid & 1;         // row arow; k-offset aq*8
    int brow = tid >> 4, bq = tid & 15;
    const __nv_bfloat16* aPh = g_Hhi + (size_t)(m0 + arow) * PP + aq * 8;
    const __nv_bfloat16* aPl = g_Hlo + (size_t)(m0 + arow) * PP + aq * 8;
    const float* bP = Wb + (size_t)brow * DIM + n0 + bq * 4;

    uint4  rah = *(const uint4*)aPh;
    uint4  ral = *(const uint4*)aPl;
    float4 rb  = *(const float4*)bP;

    wmma::fragment<wmma::accumulator, 16, 16, 16, float> acc[2][2];
    #pragma unroll
    for (int mi = 0; mi < 2; mi++)
        #pragma unroll
        for (int ni = 0; ni < 2; ni++)
            wmma::fill_fragment(acc[mi][ni], 0.0f);

    const int NK = PP / KCH;    // 32
    for (int k = 0; k < NK; k++) {
        int s = k & 1;
        __nv_bfloat16* sAhi = (__nv_bfloat16*)(smem + SAH(s));
        __nv_bfloat16* sAlo = (__nv_bfloat16*)(smem + SAL(s));
        __nv_bfloat16* sBhi = (__nv_bfloat16*)(smem + SBH(s));
        __nv_bfloat16* sBlo = (__nv_bfloat16*)(smem + SBL(s));

        {
            *(uint4*)&sAhi[arow * 24 + aq * 8] = rah;
            *(uint4*)&sAlo[arow * 24 + aq * 8] = ral;
            uint2 hi, lo;
            split4(rb, hi, lo);
            *(uint2*)&sBhi[brow * 72 + bq * 4] = hi;
            *(uint2*)&sBlo[brow * 72 + bq * 4] = lo;
        }
        __syncthreads();

        if (k + 1 < NK) {
            int k0 = (k + 1) * KCH;
            rah = *(const uint4*)(aPh + k0);
            ral = *(const uint4*)(aPl + k0);
            rb  = *(const float4*)(bP + (size_t)k0 * DIM);
        }

        wmma::fragment<wmma::matrix_a, 16, 16, 16, __nv_bfloat16, wmma::row_major> ah[2], al[2];
        wmma::fragment<wmma::matrix_b, 16, 16, 16, __nv_bfloat16, wmma::row_major> bh[2], bl[2];
        #pragma unroll
        for (int mi = 0; mi < 2; mi++) {
            wmma::load_matrix_sync(ah[mi], &sAhi[(wm * 32 + mi * 16) * 24], 24);
            wmma::load_matrix_sync(al[mi], &sAlo[(wm * 32 + mi * 16) * 24], 24);
        }
        #pragma unroll
        for (int ni = 0; ni < 2; ni++) {
            wmma::load_matrix_sync(bh[ni], &sBhi[wn * 32 + ni * 16], 72);
            wmma::load_matrix_sync(bl[ni], &sBlo[wn * 32 + ni * 16], 72);
        }
        #pragma unroll
        for (int mi = 0; mi < 2; mi++)
            #pragma unroll
            for (int ni = 0; ni < 2; ni++) {
                wmma::mma_sync(acc[mi][ni], ah[mi], bh[ni], acc[mi][ni]);
                wmma::mma_sync(acc[mi][ni], ah[mi], bl[ni], acc[mi][ni]);
                wmma::mma_sync(acc[mi][ni], al[mi], bh[ni], acc[mi][ni]);
            }
    }
    __syncthreads();

    // epilogue: acc -> smem -> gated atomicAdd into out (2 commutative adds/element)
    float* Cbuf = (float*)smem;
    #pragma unroll
    for (int mi = 0; mi < 2; mi++)
        #pragma unroll
        for (int ni = 0; ni < 2; ni++)
            wmma::store_matrix_sync(&Cbuf[(wm * 32 + mi * 16) * CBUF_LD + wn * 32 + ni * 16],
                                    acc[mi][ni], CBUF_LD, wmma::mem_row_major);
    __syncthreads();

    const float* bb = b2 + e * DIM;
    #pragma unroll
    for (int j = 0; j < 16; j++) {
        int idx = tid + 256 * j;                   // 128 rows x 32 col-pairs
        int r = idx >> 5, c = (idx & 31) * 2;
        int row = s_rowR[r];
        if (row < 0) continue;                     // padding slot
        float w = s_w[r];
        int col = n0 + c;
        float* orow = out + (size_t)row * DIM;
        atomicAdd(&orow[col],     w * (Cbuf[r * CBUF_LD + c]     + bb[col]));
        atomicAdd(&orow[col + 1], w * (Cbuf[r * CBUF_LD + c + 1] + bb[col + 1]));
    }
}

// ---------------- launch ----------------
extern "C" void kernel_launch(void* const* d_in, const int* in_sizes, int n_in,
                              void* d_out, int out_size)
{
    const float* x   = (const float*)d_in[0];
    const float* Wg  = (const float*)d_in[1];
    const float* bg  = (const float*)d_in[2];
    const float* Wp  = (const float*)d_in[3];
    const float* bp  = (const float*)d_in[4];
    const float* Wgg = (const float*)d_in[5];
    const float* bgg = (const float*)d_in[6];
    const float* W1  = (const float*)d_in[7];
    const float* b1  = (const float*)d_in[8];
    const float* W2  = (const float*)d_in[9];
    const float* b2  = (const float*)d_in[10];
    float* out = (float*)d_out;

    init_kernel<<<16384, 256>>>((float4*)out);
    route_kernel<<<BATCH, 1024>>>(x, Wg, bg, Wp, bp, Wgg, bgg);
    scan_kernel<<<1, 32>>>();
    scatter_kernel<<<(BATCH + 127) / 128, 128>>>();
    wmma_gemm1<<<dim3(PP / 64, MTILES), 256>>>(x, W1, b1);
    wmma_gemm2<<<dim3(DIM / 64, MTILES), 256>>>(W2, b2, out);
}